// round 7
// baseline (speedup 1.0000x reference)
#include <cuda_runtime.h>
#include <cstdint>

#define NN 100000
#define INF_ 128
#define OUTF 64
#define NE 1600000
#define NCHUNK ((NN + 511) / 512)   // 196

// Static device scratch (allocation-free per harness rules)
__device__ float g_support[(size_t)NN * OUTF];   // 25.6 MB
__device__ int   g_counts[NN];
__device__ int   g_rowstart[NN];
__device__ int   g_cursor[NN];
__device__ int   g_chunksum[NCHUNK];
__device__ int2  g_packed[NE];                   // 12.8 MB (col, val-bits) grouped by row

// ---------------------------------------------------------------------------
// support = X @ W.  Tiled fp32 SIMT GEMM (proven).  Also zeroes g_counts
// (safe: hist launches after this kernel completes in stream order).
// ---------------------------------------------------------------------------
__global__ __launch_bounds__(256, 2)
void gemm_kernel(const float* __restrict__ x, const float* __restrict__ w, int n) {
    __shared__ float xs[64][132];
    __shared__ float ws[128][68];

    const int tid  = threadIdx.x;
    const int brow = blockIdx.x * 64;

    // Fused: zero the histogram counters
    {
        int gi = blockIdx.x * 256 + tid;
        if (gi < NN) g_counts[gi] = 0;
    }

#pragma unroll
    for (int it = 0; it < 8; it++) {
        int i = tid + it * 256;
        int k = i >> 4;
        int c = (i & 15) << 2;
        float4 v = *(const float4*)&w[k * OUTF + c];
        *(float4*)&ws[k][c] = v;
    }
#pragma unroll
    for (int it = 0; it < 8; it++) {
        int i = tid + it * 256;
        int r = i >> 5;
        int k = (i & 31) << 2;
        int grow = brow + r;
        float4 v = make_float4(0.f, 0.f, 0.f, 0.f);
        if (grow < n) v = *(const float4*)&x[(size_t)grow * INF_ + k];
        *(float4*)&xs[r][k] = v;
    }
    __syncthreads();

    const int r0 = (tid >> 4) << 2;
    const int c0 = (tid & 15) << 2;

    float acc[4][4] = {};
#pragma unroll 4
    for (int k = 0; k < 128; k++) {
        float a0 = xs[r0 + 0][k];
        float a1 = xs[r0 + 1][k];
        float a2 = xs[r0 + 2][k];
        float a3 = xs[r0 + 3][k];
        float4 b = *(float4*)&ws[k][c0];
        acc[0][0] += a0 * b.x; acc[0][1] += a0 * b.y; acc[0][2] += a0 * b.z; acc[0][3] += a0 * b.w;
        acc[1][0] += a1 * b.x; acc[1][1] += a1 * b.y; acc[1][2] += a1 * b.z; acc[1][3] += a1 * b.w;
        acc[2][0] += a2 * b.x; acc[2][1] += a2 * b.y; acc[2][2] += a2 * b.z; acc[2][3] += a2 * b.w;
        acc[3][0] += a3 * b.x; acc[3][1] += a3 * b.y; acc[3][2] += a3 * b.z; acc[3][3] += a3 * b.w;
    }

#pragma unroll
    for (int i = 0; i < 4; i++) {
        int grow = brow + r0 + i;
        if (grow < n) {
            float4 v = make_float4(acc[i][0], acc[i][1], acc[i][2], acc[i][3]);
            *(float4*)&g_support[(size_t)grow * OUTF + c0] = v;
        }
    }
}

// ---------------------------------------------------------------------------
// Build phase: counting sort of edges by destination row
// ---------------------------------------------------------------------------
__global__ void hist_kernel(const int* __restrict__ erow) {
    int e = blockIdx.x * blockDim.x + threadIdx.x;
    if (e < NE) atomicAdd(&g_counts[__ldg(&erow[e])], 1);
}

// S1: per-chunk (512) reduction of counts -> g_chunksum[b]
__global__ __launch_bounds__(512)
void scan1_kernel() {
    __shared__ int s[512];
    int t = threadIdx.x, b = blockIdx.x;
    int i = b * 512 + t;
    s[t] = (i < NN) ? g_counts[i] : 0;
    __syncthreads();
#pragma unroll
    for (int off = 256; off > 0; off >>= 1) {
        if (t < off) s[t] += s[t + off];
        __syncthreads();
    }
    if (t == 0) g_chunksum[b] = s[0];
}

// S2: exclusive scan of chunk sums (196 values, one block)
__global__ __launch_bounds__(256)
void scan2_kernel() {
    __shared__ int s[256];
    int t = threadIdx.x;
    int v = (t < NCHUNK) ? g_chunksum[t] : 0;
    s[t] = v;
    __syncthreads();
#pragma unroll
    for (int off = 1; off < 256; off <<= 1) {
        int a = (t >= off) ? s[t - off] : 0;
        __syncthreads();
        s[t] += a;
        __syncthreads();
    }
    if (t < NCHUNK) g_chunksum[t] = s[t] - v;   // exclusive
}

// S3: per-chunk exclusive scan + chunk base -> rowstart & cursor
__global__ __launch_bounds__(512)
void scan3_kernel() {
    __shared__ int s[512];
    int t = threadIdx.x, b = blockIdx.x;
    int i = b * 512 + t;
    int v = (i < NN) ? g_counts[i] : 0;
    s[t] = v;
    __syncthreads();
#pragma unroll
    for (int off = 1; off < 512; off <<= 1) {
        int a = (t >= off) ? s[t - off] : 0;
        __syncthreads();
        s[t] += a;
        __syncthreads();
    }
    if (i < NN) {
        int excl = s[t] - v + g_chunksum[b];
        g_rowstart[i] = excl;
        g_cursor[i]   = excl;
    }
}

__global__ void fill_kernel(const int* __restrict__ erow, const int* __restrict__ ecol,
                            const float* __restrict__ evals) {
    int e = blockIdx.x * blockDim.x + threadIdx.x;
    if (e < NE) {
        int r = __ldg(&erow[e]);
        int pos = atomicAdd(&g_cursor[r], 1);
        g_packed[pos] = make_int2(__ldg(&ecol[e]), __float_as_int(__ldg(&evals[e])));
    }
}

// ---------------------------------------------------------------------------
// Pull phase: one warp per destination row.  No shuffles: all 32 lanes issue
// a warp-uniform broadcast LDG of the (col,val) entry (1 wavefront, streams
// through L1), then gather float2 per lane from support with MLP=4.
// Single plain store per lane (no atomics). bias fused.
// ---------------------------------------------------------------------------
__global__ __launch_bounds__(256)
void pull_kernel(const float* __restrict__ bias, float* __restrict__ out) {
    int wid_g = (blockIdx.x * 256 + threadIdx.x) >> 5;
    int lane  = threadIdx.x & 31;
    if (wid_g >= NN) return;

    const int row   = wid_g;
    const int start = g_rowstart[row];
    const int len   = g_counts[row];
    const int2* __restrict__ plist = g_packed + start;
    const int fo = lane * 2;

    float2 acc = *(const float2*)&bias[fo];

    int j = 0;
    for (; j + 4 <= len; j += 4) {
        // warp-uniform broadcast loads (same address across lanes)
        int2 p0 = __ldg(&plist[j + 0]);
        int2 p1 = __ldg(&plist[j + 1]);
        int2 p2 = __ldg(&plist[j + 2]);
        int2 p3 = __ldg(&plist[j + 3]);

        float2 s0 = *(const float2*)&g_support[(size_t)p0.x * OUTF + fo];
        float2 s1 = *(const float2*)&g_support[(size_t)p1.x * OUTF + fo];
        float2 s2 = *(const float2*)&g_support[(size_t)p2.x * OUTF + fo];
        float2 s3 = *(const float2*)&g_support[(size_t)p3.x * OUTF + fo];

        float v0 = __int_as_float(p0.y);
        float v1 = __int_as_float(p1.y);
        float v2 = __int_as_float(p2.y);
        float v3 = __int_as_float(p3.y);

        acc.x += s0.x * v0; acc.y += s0.y * v0;
        acc.x += s1.x * v1; acc.y += s1.y * v1;
        acc.x += s2.x * v2; acc.y += s2.y * v2;
        acc.x += s3.x * v3; acc.y += s3.y * v3;
    }
    for (; j < len; j++) {
        int2 p = __ldg(&plist[j]);
        float v = __int_as_float(p.y);
        float2 s = *(const float2*)&g_support[(size_t)p.x * OUTF + fo];
        acc.x += s.x * v; acc.y += s.y * v;
    }

    *(float2*)&out[(size_t)row * OUTF + fo] = acc;
}

// ---------------------------------------------------------------------------
extern "C" void kernel_launch(void* const* d_in, const int* in_sizes, int n_in,
                              void* d_out, int out_size) {
    const float* x     = (const float*)d_in[0];   // [100000,128]
    const float* w     = (const float*)d_in[1];   // [128,64]
    const float* bias  = (const float*)d_in[2];   // [64]
    const int*   erow  = (const int*)  d_in[3];   // [1.6M]
    const int*   ecol  = (const int*)  d_in[4];   // [1.6M]
    const float* evals = (const float*)d_in[5];   // [1.6M]
    float* out = (float*)d_out;                   // [100000,64]

    const int n = in_sizes[0] / INF_;             // 100000

    // support = X @ W (SIMT fp32) + fused zeroing of counters
    gemm_kernel<<<(n + 63) / 64, 256>>>(x, w, n);

    // Counting sort of edges by destination row
    hist_kernel<<<(NE + 255) / 256, 256>>>(erow);
    scan1_kernel<<<NCHUNK, 512>>>();
    scan2_kernel<<<1, 256>>>();
    scan3_kernel<<<NCHUNK, 512>>>();
    fill_kernel<<<(NE + 255) / 256, 256>>>(erow, ecol, evals);

    // Pull: out[row] = bias + sum(support[col] * val)
    {
        long long threads = (long long)NN * 32;
        int blocks = (int)((threads + 255) / 256);
        pull_kernel<<<blocks, 256>>>(bias, out);
    }
}